// round 1
// baseline (speedup 1.0000x reference)
#include <cuda_runtime.h>
#include <math.h>

#define N_NODES   100000
#define N_EDGES   1600000
#define N_GRAPHS  128
#define HID       128
#define N_CLASSES 10

// ---------------- scratch (static __device__, no runtime alloc) ----------------
__device__ float g_deg_out[N_NODES];
__device__ float g_deg_in [N_NODES];
__device__ float g_cs     [N_NODES];
__device__ float g_cd     [N_NODES];
__device__ float g_h1     [N_NODES];   // in_deg * cs  (layer-1 scalar message)
__device__ float g_agg1   [N_NODES];   // layer-1 scalar aggregation
__device__ float g_hs     [N_NODES * HID];  // h * cs (message rows) / final h
__device__ float g_agg    [N_NODES * HID];  // scatter-add target

// ---------------- kernels ----------------

__global__ void k_zero_small() {
    int i = blockIdx.x * blockDim.x + threadIdx.x;
    if (i < N_NODES) { g_deg_out[i] = 0.f; g_deg_in[i] = 0.f; g_agg1[i] = 0.f; }
}

__global__ void k_zero_agg() {
    // N_NODES*HID floats = N_NODES*32 float4 = 3,200,000 exactly
    int i = blockIdx.x * blockDim.x + threadIdx.x;
    ((float4*)g_agg)[i] = make_float4(0.f, 0.f, 0.f, 0.f);
}

__global__ void k_degree(const int* __restrict__ src, const int* __restrict__ dst) {
    int e = blockIdx.x * blockDim.x + threadIdx.x;
    if (e < N_EDGES) {
        atomicAdd(&g_deg_out[src[e]], 1.0f);
        atomicAdd(&g_deg_in [dst[e]], 1.0f);
    }
}

__global__ void k_prep() {
    int i = blockIdx.x * blockDim.x + threadIdx.x;
    if (i < N_NODES) {
        float od = g_deg_out[i], id = g_deg_in[i];
        float cs = rsqrtf(fmaxf(od, 1.0f));
        float cd = rsqrtf(fmaxf(id, 1.0f));
        g_cs[i] = cs; g_cd[i] = cd;
        g_h1[i] = id * cs;   // h(=in_deg) * cs
    }
}

__global__ void k_edge1(const int* __restrict__ src, const int* __restrict__ dst) {
    int e = blockIdx.x * blockDim.x + threadIdx.x;
    if (e < N_EDGES) atomicAdd(&g_agg1[dst[e]], g_h1[src[e]]);
}

// h1[n][j] = relu(agg1[n]*cd[n]*W1[j] + b1[j]);  store hs = h1 * cs
__global__ void k_expand1(const float* __restrict__ W1, const float* __restrict__ b1) {
    int idx = blockIdx.x * blockDim.x + threadIdx.x;   // exactly N_NODES*HID threads
    int n = idx >> 7, j = idx & 127;
    float x = g_agg1[n] * g_cd[n];
    float v = fmaxf(fmaf(x, W1[j], b1[j]), 0.0f);
    g_hs[idx] = v * g_cs[n];
}

// one warp per edge, float4 vector atomics (sm_90+)
__global__ void __launch_bounds__(256) k_scatter(const int* __restrict__ src,
                                                 const int* __restrict__ dst) {
    int w    = (blockIdx.x * blockDim.x + threadIdx.x) >> 5;
    int lane = threadIdx.x & 31;
    if (w >= N_EDGES) return;
    int s = __ldg(src + w);
    int d = __ldg(dst + w);
    float4 v = ((const float4*)g_hs)[s * 32 + lane];
    atomicAdd(((float4*)g_agg) + d * 32 + lane, v);
}

// out = relu((agg*cd) @ W + b) [* cs if applyCs] -> g_hs
// BM=32 nodes, N=128 cols, 256 threads, 4x4 microtile
__global__ void __launch_bounds__(256) k_gemm(const float* __restrict__ W,
                                              const float* __restrict__ bb,
                                              int applyCs) {
    __shared__ float xs[HID * 36];     // transposed x tile: xs[k*36 + n], n in [0,32)
    __shared__ float ws[32 * HID];     // 32-row chunk of W
    __shared__ float cdm[32], csm[32];

    int t = threadIdx.x;
    int nbase = blockIdx.x * 32;
    if (t < 32) { cdm[t] = g_cd[nbase + t]; csm[t] = g_cs[nbase + t]; }
    __syncthreads();

    // load x tile (32 nodes x 128), apply cd, store transposed
    #pragma unroll
    for (int i = 0; i < 16; i++) {
        int idx = t + i * 256;
        int n = idx >> 7, k = idx & 127;
        xs[k * 36 + n] = g_agg[(nbase + n) * HID + k] * cdm[n];
    }

    float acc[4][4];
    #pragma unroll
    for (int a = 0; a < 4; a++)
        #pragma unroll
        for (int c = 0; c < 4; c++) acc[a][c] = 0.f;

    int cg = (t & 31) * 4;   // column group (4 consecutive cols)
    int ng = (t >> 5) * 4;   // node group   (4 consecutive nodes)

    for (int kc = 0; kc < HID; kc += 32) {
        __syncthreads();
        #pragma unroll
        for (int i = 0; i < 4; i++) {
            int idx = t + i * 256;   // float4 index, 1024 total
            ((float4*)ws)[idx] = ((const float4*)(W + kc * HID))[idx];
        }
        __syncthreads();
        #pragma unroll
        for (int kk = 0; kk < 32; kk++) {
            float4 wv = *(const float4*)&ws[kk * HID + cg];
            float4 xv = *(const float4*)&xs[(kc + kk) * 36 + ng];
            acc[0][0] = fmaf(xv.x, wv.x, acc[0][0]);
            acc[0][1] = fmaf(xv.x, wv.y, acc[0][1]);
            acc[0][2] = fmaf(xv.x, wv.z, acc[0][2]);
            acc[0][3] = fmaf(xv.x, wv.w, acc[0][3]);
            acc[1][0] = fmaf(xv.y, wv.x, acc[1][0]);
            acc[1][1] = fmaf(xv.y, wv.y, acc[1][1]);
            acc[1][2] = fmaf(xv.y, wv.z, acc[1][2]);
            acc[1][3] = fmaf(xv.y, wv.w, acc[1][3]);
            acc[2][0] = fmaf(xv.z, wv.x, acc[2][0]);
            acc[2][1] = fmaf(xv.z, wv.y, acc[2][1]);
            acc[2][2] = fmaf(xv.z, wv.z, acc[2][2]);
            acc[2][3] = fmaf(xv.z, wv.w, acc[2][3]);
            acc[3][0] = fmaf(xv.w, wv.x, acc[3][0]);
            acc[3][1] = fmaf(xv.w, wv.y, acc[3][1]);
            acc[3][2] = fmaf(xv.w, wv.z, acc[3][2]);
            acc[3][3] = fmaf(xv.w, wv.w, acc[3][3]);
        }
    }

    float4 bv = *(const float4*)&bb[cg];
    #pragma unroll
    for (int i = 0; i < 4; i++) {
        int n = nbase + ng + i;
        float sc = applyCs ? csm[ng + i] : 1.0f;
        float4 o;
        o.x = fmaxf(acc[i][0] + bv.x, 0.f) * sc;
        o.y = fmaxf(acc[i][1] + bv.y, 0.f) * sc;
        o.z = fmaxf(acc[i][2] + bv.z, 0.f) * sc;
        o.w = fmaxf(acc[i][3] + bv.w, 0.f) * sc;
        *(float4*)&g_hs[n * HID + cg] = o;
    }
}

// per-graph mean pool of g_hs (seg sorted) -> outg[g*128 + j]
__global__ void k_pool(const int* __restrict__ seg, float* __restrict__ outg) {
    int g = blockIdx.x, j = threadIdx.x;
    int lo = 0, hi = N_NODES;
    while (lo < hi) { int m = (lo + hi) >> 1; if (seg[m] < g) lo = m + 1; else hi = m; }
    int start = lo;
    hi = N_NODES;
    while (lo < hi) { int m = (lo + hi) >> 1; if (seg[m] < g + 1) lo = m + 1; else hi = m; }
    int end = lo;
    float s = 0.f;
    for (int n = start; n < end; n++) s += g_hs[n * HID + j];
    float cnt = (float)(end - start);
    outg[g * HID + j] = s / fmaxf(cnt, 1.0f);
}

// hg = |hg1 - hg2|; logits = hg @ Wc + bc
__global__ void k_logits(const float* __restrict__ hg, const float* __restrict__ Wc,
                         const float* __restrict__ bc, float* __restrict__ outl) {
    __shared__ float dsh[HID];
    int g = blockIdx.x, t = threadIdx.x;
    dsh[t] = fabsf(hg[g * HID + t] - hg[N_GRAPHS * HID + g * HID + t]);
    __syncthreads();
    if (t < N_CLASSES) {
        float a = bc[t];
        #pragma unroll 8
        for (int k = 0; k < HID; k++) a = fmaf(dsh[k], Wc[k * N_CLASSES + t], a);
        outl[g * N_CLASSES + t] = a;
    }
}

// ---------------- launch ----------------
extern "C" void kernel_launch(void* const* d_in, const int* in_sizes, int n_in,
                              void* d_out, int out_size) {
    const int* src1 = (const int*)d_in[0];
    const int* dst1 = (const int*)d_in[1];
    const int* seg1 = (const int*)d_in[2];
    const int* src2 = (const int*)d_in[3];
    const int* dst2 = (const int*)d_in[4];
    const int* seg2 = (const int*)d_in[5];
    const float* W1 = (const float*)d_in[6];
    const float* b1 = (const float*)d_in[7];
    const float* W2 = (const float*)d_in[8];
    const float* b2 = (const float*)d_in[9];
    const float* W3 = (const float*)d_in[10];
    const float* b3 = (const float*)d_in[11];
    const float* W4 = (const float*)d_in[12];
    const float* b4 = (const float*)d_in[13];
    const float* Wc = (const float*)d_in[14];
    const float* bc = (const float*)d_in[15];
    float* out = (float*)d_out;

    const float* Ws[3] = {W2, W3, W4};
    const float* bs[3] = {b2, b3, b4};

    for (int br = 0; br < 2; br++) {
        const int* src = br ? src2 : src1;
        const int* dst = br ? dst2 : dst1;
        const int* seg = br ? seg2 : seg1;

        k_zero_small<<<(N_NODES + 255) / 256, 256>>>();
        k_degree<<<(N_EDGES + 255) / 256, 256>>>(src, dst);
        k_prep<<<(N_NODES + 255) / 256, 256>>>();
        k_edge1<<<(N_EDGES + 255) / 256, 256>>>(src, dst);
        k_expand1<<<(N_NODES * HID) / 256, 256>>>(W1, b1);

        for (int L = 0; L < 3; L++) {
            k_zero_agg<<<(N_NODES * 32) / 256, 256>>>();
            k_scatter<<<N_EDGES / 8, 256>>>(src, dst);
            k_gemm<<<N_NODES / 32, 256>>>(Ws[L], bs[L], (L < 2) ? 1 : 0);
        }
        k_pool<<<N_GRAPHS, HID>>>(seg, out + br * N_GRAPHS * HID);
    }
    k_logits<<<N_GRAPHS, HID>>>(out, Wc, bc, out + 2 * N_GRAPHS * HID);
}

// round 2
// speedup vs baseline: 1.6861x; 1.6861x over previous
#include <cuda_runtime.h>
#include <math.h>

#define N_NODES   100000
#define N_EDGES   1600000
#define N_GRAPHS  128
#define HID       128
#define N_CLASSES 10
#define NBLK      391            // ceil(N_NODES/256)

// ---------------- scratch (static __device__, no runtime alloc) ----------------
__device__ float g_deg_out[N_NODES];
__device__ float g_deg_in [N_NODES];
__device__ float g_cs     [N_NODES];
__device__ float g_cd     [N_NODES];
__device__ float g_h1     [N_NODES];        // in_deg * cs (layer-1 scalar message)
__device__ float g_agg1   [N_NODES];        // layer-1 scalar aggregation
__device__ int   g_rowtmp [N_NODES];        // per-block exclusive scan
__device__ int   g_bsum   [512];            // block sums (padded)
__device__ int   g_boff   [512];            // exclusive scan of block sums
__device__ int   g_row    [N_NODES + 1];    // CSR row offsets (by dst)
__device__ int   g_cursor [N_NODES];        // fill cursors
__device__ int   g_csr    [N_EDGES];        // CSR column indices = src node ids
__device__ float g_hsA    [N_NODES * HID];  // ping-pong feature buffers
__device__ float g_hsB    [N_NODES * HID];

// ---------------- small kernels ----------------

__global__ void k_zero_small() {
    int i = blockIdx.x * blockDim.x + threadIdx.x;
    if (i < N_NODES) { g_deg_out[i] = 0.f; g_deg_in[i] = 0.f; }
}

__global__ void k_degree(const int* __restrict__ src, const int* __restrict__ dst) {
    int e = blockIdx.x * blockDim.x + threadIdx.x;
    if (e < N_EDGES) {
        atomicAdd(&g_deg_out[src[e]], 1.0f);
        atomicAdd(&g_deg_in [dst[e]], 1.0f);
    }
}

__global__ void k_prep() {
    int i = blockIdx.x * blockDim.x + threadIdx.x;
    if (i < N_NODES) {
        float od = g_deg_out[i], id = g_deg_in[i];
        float cs = rsqrtf(fmaxf(od, 1.0f));
        float cd = rsqrtf(fmaxf(id, 1.0f));
        g_cs[i] = cs; g_cd[i] = cd;
        g_h1[i] = id * cs;
    }
}

// ---------------- CSR build: scan of in-degree, then fill ----------------

__global__ void k_scan1() {
    __shared__ int sh[256];
    int t = threadIdx.x, b = blockIdx.x;
    int i = b * 256 + t;
    int v = (i < N_NODES) ? __float2int_rn(g_deg_in[i]) : 0;
    sh[t] = v;
    __syncthreads();
    #pragma unroll
    for (int off = 1; off < 256; off <<= 1) {
        int add = (t >= off) ? sh[t - off] : 0;
        __syncthreads();
        sh[t] += add;
        __syncthreads();
    }
    if (i < N_NODES) g_rowtmp[i] = sh[t] - v;   // exclusive
    if (t == 255) g_bsum[b] = sh[255];
}

__global__ void k_scan2() {
    __shared__ int sh[512];
    int t = threadIdx.x;
    int v = (t < NBLK) ? g_bsum[t] : 0;
    sh[t] = v;
    __syncthreads();
    #pragma unroll
    for (int off = 1; off < 512; off <<= 1) {
        int add = (t >= off) ? sh[t - off] : 0;
        __syncthreads();
        sh[t] += add;
        __syncthreads();
    }
    g_boff[t] = sh[t] - v;  // exclusive
}

__global__ void k_scan3() {
    int i = blockIdx.x * blockDim.x + threadIdx.x;
    if (i < N_NODES) {
        int r = g_rowtmp[i] + g_boff[i >> 8];
        g_row[i] = r;
        g_cursor[i] = r;
    }
    if (i == 0) g_row[N_NODES] = N_EDGES;
}

__global__ void k_fill(const int* __restrict__ src, const int* __restrict__ dst) {
    int e = blockIdx.x * blockDim.x + threadIdx.x;
    if (e < N_EDGES) {
        int pos = atomicAdd(&g_cursor[dst[e]], 1);
        g_csr[pos] = src[e];
    }
}

// ---------------- layer 1 (scalar feature) ----------------

__global__ void k_agg1() {
    int n = blockIdx.x * blockDim.x + threadIdx.x;
    if (n >= N_NODES) return;
    int s = g_row[n], e = g_row[n + 1];
    float a = 0.f;
    for (int j = s; j < e; j++) a += g_h1[g_csr[j]];
    g_agg1[n] = a;
}

// hsA[n][j] = relu(agg1[n]*cd[n]*W1[j] + b1[j]) * cs[n]
__global__ void k_expand1(const float* __restrict__ W1, const float* __restrict__ b1) {
    int idx = blockIdx.x * blockDim.x + threadIdx.x;   // N_NODES*HID threads
    int n = idx >> 7, j = idx & 127;
    float x = g_agg1[n] * g_cd[n];
    float v = fmaxf(fmaf(x, W1[j], b1[j]), 0.0f);
    g_hsA[idx] = v * g_cs[n];
}

// ---------------- fused gather-aggregate + GEMM layer ----------------
// flip=0: in=hsA out=hsB ; flip=1: in=hsB out=hsA
// BM=32 nodes, 256 threads (8 warps, 4 nodes per warp), 4x4 microtile GEMM.
__global__ void __launch_bounds__(256) k_layer(int flip,
                                               const float* __restrict__ W,
                                               const float* __restrict__ bb,
                                               int applyCs) {
    __shared__ float xs[HID * 36];     // transposed x tile: xs[k*36 + n]
    __shared__ float ws[32 * HID];     // 32-row chunk of W
    __shared__ float cdm[32], csm[32];

    const float4* in4 = (const float4*)(flip ? g_hsB : g_hsA);
    float*        out = flip ? g_hsA : g_hsB;

    int t = threadIdx.x;
    int nbase = blockIdx.x * 32;
    if (t < 32) { cdm[t] = g_cd[nbase + t]; csm[t] = g_cs[nbase + t]; }
    __syncthreads();

    // ---- phase 1: CSR gather-aggregate into xs (transposed, cd applied) ----
    {
        int warp = t >> 5, lane = t & 31;
        #pragma unroll
        for (int q = 0; q < 4; q++) {
            int nl = warp * 4 + q;
            int n  = nbase + nl;
            int s  = g_row[n], e = g_row[n + 1];
            float4 acc = make_float4(0.f, 0.f, 0.f, 0.f);
            int j = s;
            for (; j + 4 <= e; j += 4) {
                int s0 = g_csr[j], s1 = g_csr[j + 1], s2 = g_csr[j + 2], s3 = g_csr[j + 3];
                float4 v0 = in4[s0 * 32 + lane];
                float4 v1 = in4[s1 * 32 + lane];
                float4 v2 = in4[s2 * 32 + lane];
                float4 v3 = in4[s3 * 32 + lane];
                acc.x += (v0.x + v1.x) + (v2.x + v3.x);
                acc.y += (v0.y + v1.y) + (v2.y + v3.y);
                acc.z += (v0.z + v1.z) + (v2.z + v3.z);
                acc.w += (v0.w + v1.w) + (v2.w + v3.w);
            }
            for (; j < e; j++) {
                float4 v = in4[g_csr[j] * 32 + lane];
                acc.x += v.x; acc.y += v.y; acc.z += v.z; acc.w += v.w;
            }
            float cdv = cdm[nl];
            int kb = lane * 4;
            xs[(kb + 0) * 36 + nl] = acc.x * cdv;
            xs[(kb + 1) * 36 + nl] = acc.y * cdv;
            xs[(kb + 2) * 36 + nl] = acc.z * cdv;
            xs[(kb + 3) * 36 + nl] = acc.w * cdv;
        }
    }
    __syncthreads();

    // ---- phase 2: GEMM out = relu(x @ W + b) [* cs] ----
    float acc[4][4];
    #pragma unroll
    for (int a = 0; a < 4; a++)
        #pragma unroll
        for (int c = 0; c < 4; c++) acc[a][c] = 0.f;

    int cg = (t & 31) * 4;   // column group
    int ng = (t >> 5) * 4;   // node group

    for (int kc = 0; kc < HID; kc += 32) {
        if (kc) __syncthreads();
        #pragma unroll
        for (int i = 0; i < 4; i++) {
            int idx = t + i * 256;   // float4 index, 1024 total
            ((float4*)ws)[idx] = ((const float4*)(W + kc * HID))[idx];
        }
        __syncthreads();
        #pragma unroll
        for (int kk = 0; kk < 32; kk++) {
            float4 wv = *(const float4*)&ws[kk * HID + cg];
            float4 xv = *(const float4*)&xs[(kc + kk) * 36 + ng];
            acc[0][0] = fmaf(xv.x, wv.x, acc[0][0]);
            acc[0][1] = fmaf(xv.x, wv.y, acc[0][1]);
            acc[0][2] = fmaf(xv.x, wv.z, acc[0][2]);
            acc[0][3] = fmaf(xv.x, wv.w, acc[0][3]);
            acc[1][0] = fmaf(xv.y, wv.x, acc[1][0]);
            acc[1][1] = fmaf(xv.y, wv.y, acc[1][1]);
            acc[1][2] = fmaf(xv.y, wv.z, acc[1][2]);
            acc[1][3] = fmaf(xv.y, wv.w, acc[1][3]);
            acc[2][0] = fmaf(xv.z, wv.x, acc[2][0]);
            acc[2][1] = fmaf(xv.z, wv.y, acc[2][1]);
            acc[2][2] = fmaf(xv.z, wv.z, acc[2][2]);
            acc[2][3] = fmaf(xv.z, wv.w, acc[2][3]);
            acc[3][0] = fmaf(xv.w, wv.x, acc[3][0]);
            acc[3][1] = fmaf(xv.w, wv.y, acc[3][1]);
            acc[3][2] = fmaf(xv.w, wv.z, acc[3][2]);
            acc[3][3] = fmaf(xv.w, wv.w, acc[3][3]);
        }
    }

    float4 bv = *(const float4*)&bb[cg];
    #pragma unroll
    for (int i = 0; i < 4; i++) {
        int n = nbase + ng + i;
        float sc = applyCs ? csm[ng + i] : 1.0f;
        float4 o;
        o.x = fmaxf(acc[i][0] + bv.x, 0.f) * sc;
        o.y = fmaxf(acc[i][1] + bv.y, 0.f) * sc;
        o.z = fmaxf(acc[i][2] + bv.z, 0.f) * sc;
        o.w = fmaxf(acc[i][3] + bv.w, 0.f) * sc;
        *(float4*)&out[n * HID + cg] = o;
    }
}

// ---------------- pooling + head ----------------

// per-graph mean pool of g_hsB (seg sorted) -> outg[g*128 + j]
__global__ void k_pool(const int* __restrict__ seg, float* __restrict__ outg) {
    int g = blockIdx.x, j = threadIdx.x;
    int lo = 0, hi = N_NODES;
    while (lo < hi) { int m = (lo + hi) >> 1; if (seg[m] < g) lo = m + 1; else hi = m; }
    int start = lo;
    hi = N_NODES;
    while (lo < hi) { int m = (lo + hi) >> 1; if (seg[m] < g + 1) lo = m + 1; else hi = m; }
    int end = lo;
    float s = 0.f;
    for (int n = start; n < end; n++) s += g_hsB[n * HID + j];
    float cnt = (float)(end - start);
    outg[g * HID + j] = s / fmaxf(cnt, 1.0f);
}

__global__ void k_logits(const float* __restrict__ hg, const float* __restrict__ Wc,
                         const float* __restrict__ bc, float* __restrict__ outl) {
    __shared__ float dsh[HID];
    int g = blockIdx.x, t = threadIdx.x;
    dsh[t] = fabsf(hg[g * HID + t] - hg[N_GRAPHS * HID + g * HID + t]);
    __syncthreads();
    if (t < N_CLASSES) {
        float a = bc[t];
        #pragma unroll 8
        for (int k = 0; k < HID; k++) a = fmaf(dsh[k], Wc[k * N_CLASSES + t], a);
        outl[g * N_CLASSES + t] = a;
    }
}

// ---------------- launch ----------------
extern "C" void kernel_launch(void* const* d_in, const int* in_sizes, int n_in,
                              void* d_out, int out_size) {
    const int* src1 = (const int*)d_in[0];
    const int* dst1 = (const int*)d_in[1];
    const int* seg1 = (const int*)d_in[2];
    const int* src2 = (const int*)d_in[3];
    const int* dst2 = (const int*)d_in[4];
    const int* seg2 = (const int*)d_in[5];
    const float* W1 = (const float*)d_in[6];
    const float* b1 = (const float*)d_in[7];
    const float* W2 = (const float*)d_in[8];
    const float* b2 = (const float*)d_in[9];
    const float* W3 = (const float*)d_in[10];
    const float* b3 = (const float*)d_in[11];
    const float* W4 = (const float*)d_in[12];
    const float* b4 = (const float*)d_in[13];
    const float* Wc = (const float*)d_in[14];
    const float* bc = (const float*)d_in[15];
    float* out = (float*)d_out;

    const float* Ws[3] = {W2, W3, W4};
    const float* bs[3] = {b2, b3, b4};

    for (int br = 0; br < 2; br++) {
        const int* src = br ? src2 : src1;
        const int* dst = br ? dst2 : dst1;
        const int* seg = br ? seg2 : seg1;

        k_zero_small<<<NBLK, 256>>>();
        k_degree<<<(N_EDGES + 255) / 256, 256>>>(src, dst);
        k_prep<<<NBLK, 256>>>();

        // CSR build (by destination)
        k_scan1<<<NBLK, 256>>>();
        k_scan2<<<1, 512>>>();
        k_scan3<<<NBLK, 256>>>();
        k_fill<<<(N_EDGES + 255) / 256, 256>>>(src, dst);

        // layer 1 (scalar input feature)
        k_agg1<<<NBLK, 256>>>();
        k_expand1<<<(N_NODES * HID) / 256, 256>>>(W1, b1);

        // layers 2-4: fused gather + GEMM, ping-pong A->B->A->B
        for (int L = 0; L < 3; L++) {
            k_layer<<<N_NODES / 32, 256>>>(L & 1, Ws[L], bs[L], (L < 2) ? 1 : 0);
        }
        k_pool<<<N_GRAPHS, HID>>>(seg, out + br * N_GRAPHS * HID);
    }
    k_logits<<<N_GRAPHS, HID>>>(out, Wc, bc, out + 2 * N_GRAPHS * HID);
}

// round 3
// speedup vs baseline: 1.9511x; 1.1572x over previous
#include <cuda_runtime.h>
#include <math.h>
#include <stdint.h>

#define N_NODES   100000
#define N_EDGES   1600000
#define N_GRAPHS  128
#define HID       128
#define N_CLASSES 10
#define NBLK      391            // ceil(N_NODES/256)
#define BM        64             // nodes per k_layer block
#define LGRID     ((N_NODES + BM - 1) / BM)

// ---------------- scratch (static __device__, no runtime alloc) ----------------
__device__ float g_deg_out[N_NODES];
__device__ float g_deg_in [N_NODES];
__device__ float g_cs     [N_NODES];
__device__ float g_cd     [N_NODES];
__device__ float g_h1     [N_NODES];
__device__ float g_agg1   [N_NODES];
__device__ int   g_rowtmp [N_NODES];
__device__ int   g_bsum   [512];
__device__ int   g_boff   [512];
__device__ int   g_row    [N_NODES + 1];
__device__ int   g_cursor [N_NODES];
__device__ int   g_csr    [N_EDGES];
__device__ float g_hsA    [N_NODES * HID];
__device__ float g_hsB    [N_NODES * HID];

// ---------------- f32x2 packed-math helpers (sm_103a) ----------------
#define FMA2(acc, x, w) \
    asm("fma.rn.f32x2 %0, %1, %2, %3;" : "=l"(acc) : "l"(x), "l"(w), "l"(acc))
#define PACKDUP(d, f) \
    asm("mov.b64 %0, {%1, %1};" : "=l"(d) : "r"(__float_as_uint(f)))
#define UNPACK2(lo, hi, v) \
    asm("mov.b64 {%0, %1}, %2;" : "=r"(lo), "=r"(hi) : "l"(v))

// ---------------- small kernels ----------------

__global__ void k_zero_small() {
    int i = blockIdx.x * blockDim.x + threadIdx.x;
    if (i < N_NODES) { g_deg_out[i] = 0.f; g_deg_in[i] = 0.f; }
}

__global__ void k_degree(const int* __restrict__ src, const int* __restrict__ dst) {
    int e = blockIdx.x * blockDim.x + threadIdx.x;
    if (e < N_EDGES) {
        atomicAdd(&g_deg_out[src[e]], 1.0f);
        atomicAdd(&g_deg_in [dst[e]], 1.0f);
    }
}

__global__ void k_prep() {
    int i = blockIdx.x * blockDim.x + threadIdx.x;
    if (i < N_NODES) {
        float od = g_deg_out[i], id = g_deg_in[i];
        float cs = rsqrtf(fmaxf(od, 1.0f));
        float cd = rsqrtf(fmaxf(id, 1.0f));
        g_cs[i] = cs; g_cd[i] = cd;
        g_h1[i] = id * cs;
    }
}

// ---------------- CSR build ----------------

__global__ void k_scan1() {
    __shared__ int sh[256];
    int t = threadIdx.x, b = blockIdx.x;
    int i = b * 256 + t;
    int v = (i < N_NODES) ? __float2int_rn(g_deg_in[i]) : 0;
    sh[t] = v;
    __syncthreads();
    #pragma unroll
    for (int off = 1; off < 256; off <<= 1) {
        int add = (t >= off) ? sh[t - off] : 0;
        __syncthreads();
        sh[t] += add;
        __syncthreads();
    }
    if (i < N_NODES) g_rowtmp[i] = sh[t] - v;
    if (t == 255) g_bsum[b] = sh[255];
}

__global__ void k_scan2() {
    __shared__ int sh[512];
    int t = threadIdx.x;
    int v = (t < NBLK) ? g_bsum[t] : 0;
    sh[t] = v;
    __syncthreads();
    #pragma unroll
    for (int off = 1; off < 512; off <<= 1) {
        int add = (t >= off) ? sh[t - off] : 0;
        __syncthreads();
        sh[t] += add;
        __syncthreads();
    }
    g_boff[t] = sh[t] - v;
}

__global__ void k_scan3() {
    int i = blockIdx.x * blockDim.x + threadIdx.x;
    if (i < N_NODES) {
        int r = g_rowtmp[i] + g_boff[i >> 8];
        g_row[i] = r;
        g_cursor[i] = r;
    }
    if (i == 0) g_row[N_NODES] = N_EDGES;
}

__global__ void k_fill(const int* __restrict__ src, const int* __restrict__ dst) {
    int e = blockIdx.x * blockDim.x + threadIdx.x;
    if (e < N_EDGES) {
        int pos = atomicAdd(&g_cursor[dst[e]], 1);
        g_csr[pos] = src[e];
    }
}

// ---------------- layer 1 (scalar feature) ----------------

__global__ void k_agg1() {
    int n = blockIdx.x * blockDim.x + threadIdx.x;
    if (n >= N_NODES) return;
    int s = g_row[n], e = g_row[n + 1];
    float a = 0.f;
    for (int j = s; j < e; j++) a += g_h1[g_csr[j]];
    g_agg1[n] = a;
}

__global__ void k_expand1(const float* __restrict__ W1, const float* __restrict__ b1) {
    int idx = blockIdx.x * blockDim.x + threadIdx.x;
    int n = idx >> 7, j = idx & 127;
    float x = g_agg1[n] * g_cd[n];
    float v = fmaxf(fmaf(x, W1[j], b1[j]), 0.0f);
    g_hsA[idx] = v * g_cs[n];
}

// ---------------- fused gather-aggregate + packed-FFMA2 GEMM layer ----------------
// flip=0: in=hsA out=hsB ; flip=1: in=hsB out=hsA
// BM=64 nodes, 256 threads (8 warps, 8 nodes per warp).
// GEMM microtile: 8 nodes x 4 cols per thread, f32x2 acc paired over nodes.
__global__ void __launch_bounds__(256) k_layer(int flip,
                                               const float* __restrict__ W,
                                               const float* __restrict__ bb,
                                               int applyCs) {
    __shared__ float xs[HID * 68];     // xs[k*68 + n], n in [0,64); 34816 B
    __shared__ float ws[16 * HID];     // 16-row chunk of W; 8192 B
    __shared__ float cdm[BM], csm[BM];

    const float4* in4 = (const float4*)(flip ? g_hsB : g_hsA);
    float*        out = flip ? g_hsA : g_hsB;

    int t = threadIdx.x;
    int nbase = blockIdx.x * BM;
    if (t < BM) {
        int n = nbase + t;
        cdm[t] = (n < N_NODES) ? g_cd[n] : 0.f;
        csm[t] = (n < N_NODES) ? g_cs[n] : 0.f;
    }
    __syncthreads();

    // ---- phase 1: CSR gather-aggregate into xs (transposed, cd applied) ----
    {
        int warp = t >> 5, lane = t & 31;
        #pragma unroll
        for (int q = 0; q < 8; q++) {
            int nl = warp * 8 + q;
            int n  = nbase + nl;
            float4 acc = make_float4(0.f, 0.f, 0.f, 0.f);
            if (n < N_NODES) {
                int s = g_row[n], e = g_row[n + 1];
                int j = s;
                for (; j + 4 <= e; j += 4) {
                    int s0 = g_csr[j], s1 = g_csr[j + 1], s2 = g_csr[j + 2], s3 = g_csr[j + 3];
                    float4 v0 = in4[s0 * 32 + lane];
                    float4 v1 = in4[s1 * 32 + lane];
                    float4 v2 = in4[s2 * 32 + lane];
                    float4 v3 = in4[s3 * 32 + lane];
                    acc.x += (v0.x + v1.x) + (v2.x + v3.x);
                    acc.y += (v0.y + v1.y) + (v2.y + v3.y);
                    acc.z += (v0.z + v1.z) + (v2.z + v3.z);
                    acc.w += (v0.w + v1.w) + (v2.w + v3.w);
                }
                for (; j < e; j++) {
                    float4 v = in4[g_csr[j] * 32 + lane];
                    acc.x += v.x; acc.y += v.y; acc.z += v.z; acc.w += v.w;
                }
            }
            float cdv = cdm[nl];
            int kb = lane * 4;
            xs[(kb + 0) * 68 + nl] = acc.x * cdv;
            xs[(kb + 1) * 68 + nl] = acc.y * cdv;
            xs[(kb + 2) * 68 + nl] = acc.z * cdv;
            xs[(kb + 3) * 68 + nl] = acc.w * cdv;
        }
    }
    __syncthreads();

    // ---- phase 2: GEMM out = relu(x @ W + b) [* cs], packed f32x2 ----
    uint64_t acc2[4][4];   // [node-pair p][col c]; lo = node ng+2p, hi = node ng+2p+1
    #pragma unroll
    for (int p = 0; p < 4; p++)
        #pragma unroll
        for (int c = 0; c < 4; c++) acc2[p][c] = 0ull;

    int cg = (t & 31) * 4;   // column group (4 consecutive cols)
    int ng = (t >> 5) * 8;   // node group   (8 consecutive nodes)

    for (int kc = 0; kc < HID; kc += 16) {
        if (kc) __syncthreads();
        #pragma unroll
        for (int i = 0; i < 2; i++) {
            int idx = t + i * 256;   // float4 index, 512 total
            ((float4*)ws)[idx] = ((const float4*)(W + kc * HID))[idx];
        }
        __syncthreads();
        #pragma unroll
        for (int kk = 0; kk < 16; kk++) {
            float4 wv = *(const float4*)&ws[kk * HID + cg];
            uint64_t wd0, wd1, wd2, wd3;
            PACKDUP(wd0, wv.x); PACKDUP(wd1, wv.y);
            PACKDUP(wd2, wv.z); PACKDUP(wd3, wv.w);
            const float* xrow = &xs[(kc + kk) * 68 + ng];
            ulonglong2 xa = *(const ulonglong2*)(xrow);       // {n0,n1},{n2,n3}
            ulonglong2 xb = *(const ulonglong2*)(xrow + 4);   // {n4,n5},{n6,n7}
            FMA2(acc2[0][0], xa.x, wd0); FMA2(acc2[0][1], xa.x, wd1);
            FMA2(acc2[0][2], xa.x, wd2); FMA2(acc2[0][3], xa.x, wd3);
            FMA2(acc2[1][0], xa.y, wd0); FMA2(acc2[1][1], xa.y, wd1);
            FMA2(acc2[1][2], xa.y, wd2); FMA2(acc2[1][3], xa.y, wd3);
            FMA2(acc2[2][0], xb.x, wd0); FMA2(acc2[2][1], xb.x, wd1);
            FMA2(acc2[2][2], xb.x, wd2); FMA2(acc2[2][3], xb.x, wd3);
            FMA2(acc2[3][0], xb.y, wd0); FMA2(acc2[3][1], xb.y, wd1);
            FMA2(acc2[3][2], xb.y, wd2); FMA2(acc2[3][3], xb.y, wd3);
        }
    }

    float4 bv = *(const float4*)&bb[cg];
    #pragma unroll
    for (int p = 0; p < 4; p++) {
        int nl0 = ng + 2 * p;
        uint32_t lo0, hi0, lo1, hi1, lo2, hi2, lo3, hi3;
        UNPACK2(lo0, hi0, acc2[p][0]);
        UNPACK2(lo1, hi1, acc2[p][1]);
        UNPACK2(lo2, hi2, acc2[p][2]);
        UNPACK2(lo3, hi3, acc2[p][3]);
        int n0 = nbase + nl0, n1 = n0 + 1;
        if (n0 < N_NODES) {
            float sc = applyCs ? csm[nl0] : 1.0f;
            float4 o;
            o.x = fmaxf(__uint_as_float(lo0) + bv.x, 0.f) * sc;
            o.y = fmaxf(__uint_as_float(lo1) + bv.y, 0.f) * sc;
            o.z = fmaxf(__uint_as_float(lo2) + bv.z, 0.f) * sc;
            o.w = fmaxf(__uint_as_float(lo3) + bv.w, 0.f) * sc;
            *(float4*)&out[n0 * HID + cg] = o;
        }
        if (n1 < N_NODES) {
            float sc = applyCs ? csm[nl0 + 1] : 1.0f;
            float4 o;
            o.x = fmaxf(__uint_as_float(hi0) + bv.x, 0.f) * sc;
            o.y = fmaxf(__uint_as_float(hi1) + bv.y, 0.f) * sc;
            o.z = fmaxf(__uint_as_float(hi2) + bv.z, 0.f) * sc;
            o.w = fmaxf(__uint_as_float(hi3) + bv.w, 0.f) * sc;
            *(float4*)&out[n1 * HID + cg] = o;
        }
    }
}

// ---------------- pooling + head ----------------

__global__ void k_pool(const int* __restrict__ seg, float* __restrict__ outg) {
    int g = blockIdx.x, j = threadIdx.x;
    int lo = 0, hi = N_NODES;
    while (lo < hi) { int m = (lo + hi) >> 1; if (seg[m] < g) lo = m + 1; else hi = m; }
    int start = lo;
    hi = N_NODES;
    while (lo < hi) { int m = (lo + hi) >> 1; if (seg[m] < g + 1) lo = m + 1; else hi = m; }
    int end = lo;
    float s = 0.f;
    for (int n = start; n < end; n++) s += g_hsB[n * HID + j];
    float cnt = (float)(end - start);
    outg[g * HID + j] = s / fmaxf(cnt, 1.0f);
}

__global__ void k_logits(const float* __restrict__ hg, const float* __restrict__ Wc,
                         const float* __restrict__ bc, float* __restrict__ outl) {
    __shared__ float dsh[HID];
    int g = blockIdx.x, t = threadIdx.x;
    dsh[t] = fabsf(hg[g * HID + t] - hg[N_GRAPHS * HID + g * HID + t]);
    __syncthreads();
    if (t < N_CLASSES) {
        float a = bc[t];
        #pragma unroll 8
        for (int k = 0; k < HID; k++) a = fmaf(dsh[k], Wc[k * N_CLASSES + t], a);
        outl[g * N_CLASSES + t] = a;
    }
}

// ---------------- launch ----------------
extern "C" void kernel_launch(void* const* d_in, const int* in_sizes, int n_in,
                              void* d_out, int out_size) {
    const int* src1 = (const int*)d_in[0];
    const int* dst1 = (const int*)d_in[1];
    const int* seg1 = (const int*)d_in[2];
    const int* src2 = (const int*)d_in[3];
    const int* dst2 = (const int*)d_in[4];
    const int* seg2 = (const int*)d_in[5];
    const float* W1 = (const float*)d_in[6];
    const float* b1 = (const float*)d_in[7];
    const float* W2 = (const float*)d_in[8];
    const float* b2 = (const float*)d_in[9];
    const float* W3 = (const float*)d_in[10];
    const float* b3 = (const float*)d_in[11];
    const float* W4 = (const float*)d_in[12];
    const float* b4 = (const float*)d_in[13];
    const float* Wc = (const float*)d_in[14];
    const float* bc = (const float*)d_in[15];
    float* out = (float*)d_out;

    const float* Ws[3] = {W2, W3, W4};
    const float* bs[3] = {b2, b3, b4};

    for (int br = 0; br < 2; br++) {
        const int* src = br ? src2 : src1;
        const int* dst = br ? dst2 : dst1;
        const int* seg = br ? seg2 : seg1;

        k_zero_small<<<NBLK, 256>>>();
        k_degree<<<(N_EDGES + 255) / 256, 256>>>(src, dst);
        k_prep<<<NBLK, 256>>>();

        k_scan1<<<NBLK, 256>>>();
        k_scan2<<<1, 512>>>();
        k_scan3<<<NBLK, 256>>>();
        k_fill<<<(N_EDGES + 255) / 256, 256>>>(src, dst);

        k_agg1<<<NBLK, 256>>>();
        k_expand1<<<(N_NODES * HID) / 256, 256>>>(W1, b1);

        for (int L = 0; L < 3; L++) {
            k_layer<<<LGRID, 256>>>(L & 1, Ws[L], bs[L], (L < 2) ? 1 : 0);
        }
        k_pool<<<N_GRAPHS, HID>>>(seg, out + br * N_GRAPHS * HID);
    }
    k_logits<<<N_GRAPHS, HID>>>(out, Wc, bc, out + 2 * N_GRAPHS * HID);
}

// round 4
// speedup vs baseline: 2.2653x; 1.1610x over previous
#include <cuda_runtime.h>
#include <math.h>
#include <stdint.h>

#define N_NODES   100000
#define N_EDGES   1600000
#define N_GRAPHS  128
#define HID       128
#define N_CLASSES 10
#define NBLK      391            // ceil(N_NODES/256)
#define BM        64             // nodes per layer block
#define LGRID     ((N_NODES + BM - 1) / BM)
#define NSPLIT    16             // pool node-range splits per graph

// ---------------- scratch (static __device__, no runtime alloc) ----------------
__device__ float  g_deg_out[N_NODES];
__device__ float  g_deg_in [N_NODES];
__device__ float  g_cs     [N_NODES];
__device__ float  g_cd     [N_NODES];
__device__ float  g_h1     [N_NODES];
__device__ float2 g_x1cs   [N_NODES];       // {agg1*cd, cs} for rank-1 layer-2 gather
__device__ int    g_rowtmp [N_NODES];
__device__ int    g_bsum   [512];
__device__ int    g_boff   [512];
__device__ int    g_row    [N_NODES + 1];
__device__ int    g_cursor [N_NODES];
__device__ int    g_csr    [N_EDGES];
__device__ float  g_hsA    [N_NODES * HID];
__device__ float  g_hsB    [N_NODES * HID];

// ---------------- f32x2 packed-math helpers (sm_103a) ----------------
#define FMA2(acc, x, w) \
    asm("fma.rn.f32x2 %0, %1, %2, %3;" : "=l"(acc) : "l"(x), "l"(w), "l"(acc))
#define PACKDUP(d, f) \
    asm("mov.b64 %0, {%1, %1};" : "=l"(d) : "r"(__float_as_uint(f)))
#define UNPACK2(lo, hi, v) \
    asm("mov.b64 {%0, %1}, %2;" : "=r"(lo), "=r"(hi) : "l"(v))

// ---------------- small kernels ----------------

__global__ void k_zero_out(float* __restrict__ out) {
    int i = blockIdx.x * blockDim.x + threadIdx.x;   // 2*N_GRAPHS*HID = 32768
    out[i] = 0.f;
}

__global__ void k_zero_small() {
    int i = blockIdx.x * blockDim.x + threadIdx.x;
    if (i < N_NODES) { g_deg_out[i] = 0.f; g_deg_in[i] = 0.f; }
}

__global__ void k_degree(const int* __restrict__ src, const int* __restrict__ dst) {
    int e = blockIdx.x * blockDim.x + threadIdx.x;
    if (e < N_EDGES) {
        atomicAdd(&g_deg_out[src[e]], 1.0f);
        atomicAdd(&g_deg_in [dst[e]], 1.0f);
    }
}

// ---------------- CSR build (prep fused into scan1) ----------------

__global__ void k_scan1() {
    __shared__ int sh[256];
    int t = threadIdx.x, b = blockIdx.x;
    int i = b * 256 + t;
    int v = 0;
    if (i < N_NODES) {
        float od = g_deg_out[i], id = g_deg_in[i];
        float cs = rsqrtf(fmaxf(od, 1.0f));
        float cd = rsqrtf(fmaxf(id, 1.0f));
        g_cs[i] = cs; g_cd[i] = cd;
        g_h1[i] = id * cs;
        v = __float2int_rn(id);
    }
    sh[t] = v;
    __syncthreads();
    #pragma unroll
    for (int off = 1; off < 256; off <<= 1) {
        int add = (t >= off) ? sh[t - off] : 0;
        __syncthreads();
        sh[t] += add;
        __syncthreads();
    }
    if (i < N_NODES) g_rowtmp[i] = sh[t] - v;
    if (t == 255) g_bsum[b] = sh[255];
}

__global__ void k_scan2() {
    __shared__ int sh[512];
    int t = threadIdx.x;
    int v = (t < NBLK) ? g_bsum[t] : 0;
    sh[t] = v;
    __syncthreads();
    #pragma unroll
    for (int off = 1; off < 512; off <<= 1) {
        int add = (t >= off) ? sh[t - off] : 0;
        __syncthreads();
        sh[t] += add;
        __syncthreads();
    }
    g_boff[t] = sh[t] - v;
}

__global__ void k_scan3() {
    int i = blockIdx.x * blockDim.x + threadIdx.x;
    if (i < N_NODES) {
        int r = g_rowtmp[i] + g_boff[i >> 8];
        g_row[i] = r;
        g_cursor[i] = r;
    }
    if (i == 0) g_row[N_NODES] = N_EDGES;
}

__global__ void k_fill(const int* __restrict__ src, const int* __restrict__ dst) {
    int e = blockIdx.x * blockDim.x + threadIdx.x;
    if (e < N_EDGES) {
        int pos = atomicAdd(&g_cursor[dst[e]], 1);
        g_csr[pos] = src[e];
    }
}

// layer-1 scalar aggregation; pack {x1 = agg*cd, cs} for the rank-1 layer-2 gather
__global__ void k_agg1() {
    int n = blockIdx.x * blockDim.x + threadIdx.x;
    if (n >= N_NODES) return;
    int s = g_row[n], e = g_row[n + 1];
    float a = 0.f;
    for (int j = s; j < e; j++) a += g_h1[g_csr[j]];
    g_x1cs[n] = make_float2(a * g_cd[n], g_cs[n]);
}

// ---------------- shared GEMM phase (packed f32x2) ----------------
// xs[k*68 + n] holds the 64-node x tile (cd applied). out = relu(x@W+b)[*cs]
__device__ __forceinline__ void gemm_phase(const float* __restrict__ W,
                                           const float* __restrict__ bb,
                                           float* xs, float* ws,
                                           const float* csm, float* out,
                                           int nbase, int applyCs, int t) {
    uint64_t acc2[4][4];
    #pragma unroll
    for (int p = 0; p < 4; p++)
        #pragma unroll
        for (int c = 0; c < 4; c++) acc2[p][c] = 0ull;

    int cg = (t & 31) * 4;
    int ng = (t >> 5) * 8;

    for (int kc = 0; kc < HID; kc += 16) {
        if (kc) __syncthreads();
        #pragma unroll
        for (int i = 0; i < 2; i++) {
            int idx = t + i * 256;
            ((float4*)ws)[idx] = ((const float4*)(W + kc * HID))[idx];
        }
        __syncthreads();
        #pragma unroll
        for (int kk = 0; kk < 16; kk++) {
            float4 wv = *(const float4*)&ws[kk * HID + cg];
            uint64_t wd0, wd1, wd2, wd3;
            PACKDUP(wd0, wv.x); PACKDUP(wd1, wv.y);
            PACKDUP(wd2, wv.z); PACKDUP(wd3, wv.w);
            const float* xrow = &xs[(kc + kk) * 68 + ng];
            ulonglong2 xa = *(const ulonglong2*)(xrow);
            ulonglong2 xb = *(const ulonglong2*)(xrow + 4);
            FMA2(acc2[0][0], xa.x, wd0); FMA2(acc2[0][1], xa.x, wd1);
            FMA2(acc2[0][2], xa.x, wd2); FMA2(acc2[0][3], xa.x, wd3);
            FMA2(acc2[1][0], xa.y, wd0); FMA2(acc2[1][1], xa.y, wd1);
            FMA2(acc2[1][2], xa.y, wd2); FMA2(acc2[1][3], xa.y, wd3);
            FMA2(acc2[2][0], xb.x, wd0); FMA2(acc2[2][1], xb.x, wd1);
            FMA2(acc2[2][2], xb.x, wd2); FMA2(acc2[2][3], xb.x, wd3);
            FMA2(acc2[3][0], xb.y, wd0); FMA2(acc2[3][1], xb.y, wd1);
            FMA2(acc2[3][2], xb.y, wd2); FMA2(acc2[3][3], xb.y, wd3);
        }
    }

    float4 bv = *(const float4*)&bb[cg];
    #pragma unroll
    for (int p = 0; p < 4; p++) {
        int nl0 = ng + 2 * p;
        uint32_t lo0, hi0, lo1, hi1, lo2, hi2, lo3, hi3;
        UNPACK2(lo0, hi0, acc2[p][0]);
        UNPACK2(lo1, hi1, acc2[p][1]);
        UNPACK2(lo2, hi2, acc2[p][2]);
        UNPACK2(lo3, hi3, acc2[p][3]);
        int n0 = nbase + nl0, n1 = n0 + 1;
        if (n0 < N_NODES) {
            float sc = applyCs ? csm[nl0] : 1.0f;
            float4 o;
            o.x = fmaxf(__uint_as_float(lo0) + bv.x, 0.f) * sc;
            o.y = fmaxf(__uint_as_float(lo1) + bv.y, 0.f) * sc;
            o.z = fmaxf(__uint_as_float(lo2) + bv.z, 0.f) * sc;
            o.w = fmaxf(__uint_as_float(lo3) + bv.w, 0.f) * sc;
            *(float4*)&out[n0 * HID + cg] = o;
        }
        if (n1 < N_NODES) {
            float sc = applyCs ? csm[nl0 + 1] : 1.0f;
            float4 o;
            o.x = fmaxf(__uint_as_float(hi0) + bv.x, 0.f) * sc;
            o.y = fmaxf(__uint_as_float(hi1) + bv.y, 0.f) * sc;
            o.z = fmaxf(__uint_as_float(hi2) + bv.z, 0.f) * sc;
            o.w = fmaxf(__uint_as_float(hi3) + bv.w, 0.f) * sc;
            *(float4*)&out[n1 * HID + cg] = o;
        }
    }
}

// ---------------- layer 2 (W2): rank-1 reconstruct gather + GEMM -> hsA ----------------
__global__ void __launch_bounds__(256) k_layer_first(const float* __restrict__ W1,
                                                     const float* __restrict__ B1,
                                                     const float* __restrict__ W,
                                                     const float* __restrict__ bb) {
    __shared__ float xs[HID * 68];
    __shared__ float ws[16 * HID];
    __shared__ float cdm[BM], csm[BM];

    int t = threadIdx.x;
    int nbase = blockIdx.x * BM;
    if (t < BM) {
        int n = nbase + t;
        cdm[t] = (n < N_NODES) ? g_cd[n] : 0.f;
        csm[t] = (n < N_NODES) ? g_cs[n] : 0.f;
    }
    __syncthreads();

    {
        int warp = t >> 5, lane = t & 31;
        int kb = lane * 4;
        float4 w1  = *(const float4*)(W1 + kb);
        float4 b1v = *(const float4*)(B1 + kb);
        #pragma unroll
        for (int q = 0; q < 8; q++) {
            int nl = warp * 8 + q;
            int n  = nbase + nl;
            float4 acc = make_float4(0.f, 0.f, 0.f, 0.f);
            if (n < N_NODES) {
                int s = g_row[n], e = g_row[n + 1];
                int j = s;
                for (; j + 4 <= e; j += 4) {
                    int s0 = g_csr[j], s1 = g_csr[j+1], s2 = g_csr[j+2], s3 = g_csr[j+3];
                    float2 p0 = g_x1cs[s0];
                    float2 p1 = g_x1cs[s1];
                    float2 p2 = g_x1cs[s2];
                    float2 p3 = g_x1cs[s3];
                    acc.x += fmaxf(fmaf(p0.x, w1.x, b1v.x), 0.f) * p0.y
                           + fmaxf(fmaf(p1.x, w1.x, b1v.x), 0.f) * p1.y
                           + fmaxf(fmaf(p2.x, w1.x, b1v.x), 0.f) * p2.y
                           + fmaxf(fmaf(p3.x, w1.x, b1v.x), 0.f) * p3.y;
                    acc.y += fmaxf(fmaf(p0.x, w1.y, b1v.y), 0.f) * p0.y
                           + fmaxf(fmaf(p1.x, w1.y, b1v.y), 0.f) * p1.y
                           + fmaxf(fmaf(p2.x, w1.y, b1v.y), 0.f) * p2.y
                           + fmaxf(fmaf(p3.x, w1.y, b1v.y), 0.f) * p3.y;
                    acc.z += fmaxf(fmaf(p0.x, w1.z, b1v.z), 0.f) * p0.y
                           + fmaxf(fmaf(p1.x, w1.z, b1v.z), 0.f) * p1.y
                           + fmaxf(fmaf(p2.x, w1.z, b1v.z), 0.f) * p2.y
                           + fmaxf(fmaf(p3.x, w1.z, b1v.z), 0.f) * p3.y;
                    acc.w += fmaxf(fmaf(p0.x, w1.w, b1v.w), 0.f) * p0.y
                           + fmaxf(fmaf(p1.x, w1.w, b1v.w), 0.f) * p1.y
                           + fmaxf(fmaf(p2.x, w1.w, b1v.w), 0.f) * p2.y
                           + fmaxf(fmaf(p3.x, w1.w, b1v.w), 0.f) * p3.y;
                }
                for (; j < e; j++) {
                    float2 p = g_x1cs[g_csr[j]];
                    acc.x += fmaxf(fmaf(p.x, w1.x, b1v.x), 0.f) * p.y;
                    acc.y += fmaxf(fmaf(p.x, w1.y, b1v.y), 0.f) * p.y;
                    acc.z += fmaxf(fmaf(p.x, w1.z, b1v.z), 0.f) * p.y;
                    acc.w += fmaxf(fmaf(p.x, w1.w, b1v.w), 0.f) * p.y;
                }
            }
            float cdv = cdm[nl];
            xs[(kb + 0) * 68 + nl] = acc.x * cdv;
            xs[(kb + 1) * 68 + nl] = acc.y * cdv;
            xs[(kb + 2) * 68 + nl] = acc.z * cdv;
            xs[(kb + 3) * 68 + nl] = acc.w * cdv;
        }
    }
    __syncthreads();

    gemm_phase(W, bb, xs, ws, csm, g_hsA, nbase, 1, t);
}

// ---------------- layers 3/4: row gather + GEMM ----------------
// flip=0: in=hsA out=hsB ; flip=1: in=hsB out=hsA
__global__ void __launch_bounds__(256) k_layer(int flip,
                                               const float* __restrict__ W,
                                               const float* __restrict__ bb,
                                               int applyCs) {
    __shared__ float xs[HID * 68];
    __shared__ float ws[16 * HID];
    __shared__ float cdm[BM], csm[BM];

    const float4* in4 = (const float4*)(flip ? g_hsB : g_hsA);
    float*        out = flip ? g_hsA : g_hsB;

    int t = threadIdx.x;
    int nbase = blockIdx.x * BM;
    if (t < BM) {
        int n = nbase + t;
        cdm[t] = (n < N_NODES) ? g_cd[n] : 0.f;
        csm[t] = (n < N_NODES) ? g_cs[n] : 0.f;
    }
    __syncthreads();

    {
        int warp = t >> 5, lane = t & 31;
        #pragma unroll
        for (int q = 0; q < 8; q++) {
            int nl = warp * 8 + q;
            int n  = nbase + nl;
            float4 acc = make_float4(0.f, 0.f, 0.f, 0.f);
            if (n < N_NODES) {
                int s = g_row[n], e = g_row[n + 1];
                int j = s;
                for (; j + 4 <= e; j += 4) {
                    int s0 = g_csr[j], s1 = g_csr[j+1], s2 = g_csr[j+2], s3 = g_csr[j+3];
                    float4 v0 = in4[s0 * 32 + lane];
                    float4 v1 = in4[s1 * 32 + lane];
                    float4 v2 = in4[s2 * 32 + lane];
                    float4 v3 = in4[s3 * 32 + lane];
                    acc.x += (v0.x + v1.x) + (v2.x + v3.x);
                    acc.y += (v0.y + v1.y) + (v2.y + v3.y);
                    acc.z += (v0.z + v1.z) + (v2.z + v3.z);
                    acc.w += (v0.w + v1.w) + (v2.w + v3.w);
                }
                for (; j < e; j++) {
                    float4 v = in4[g_csr[j] * 32 + lane];
                    acc.x += v.x; acc.y += v.y; acc.z += v.z; acc.w += v.w;
                }
            }
            float cdv = cdm[nl];
            int kb = lane * 4;
            xs[(kb + 0) * 68 + nl] = acc.x * cdv;
            xs[(kb + 1) * 68 + nl] = acc.y * cdv;
            xs[(kb + 2) * 68 + nl] = acc.z * cdv;
            xs[(kb + 3) * 68 + nl] = acc.w * cdv;
        }
    }
    __syncthreads();

    gemm_phase(W, bb, xs, ws, csm, out, nbase, applyCs, t);
}

// ---------------- pooling (parallel, atomic partials into pre-zeroed out) ----------------

__global__ void k_pool(const int* __restrict__ seg, float* __restrict__ outg) {
    int g = blockIdx.x, slice = blockIdx.y, j = threadIdx.x;
    int lo = 0, hi = N_NODES;
    while (lo < hi) { int m = (lo + hi) >> 1; if (seg[m] < g) lo = m + 1; else hi = m; }
    int start = lo;
    hi = N_NODES;
    while (lo < hi) { int m = (lo + hi) >> 1; if (seg[m] < g + 1) lo = m + 1; else hi = m; }
    int end = lo;
    int len = end - start;
    int s0 = start + (int)(((long long)len * slice) / NSPLIT);
    int s1 = start + (int)(((long long)len * (slice + 1)) / NSPLIT);
    float s = 0.f;
    for (int n = s0; n < s1; n++) s += g_hsA[n * HID + j];
    if (s1 > s0) atomicAdd(&outg[g * HID + j], s);
}

__global__ void k_pooldiv(const int* __restrict__ seg, float* __restrict__ outg) {
    int g = blockIdx.x, j = threadIdx.x;
    int lo = 0, hi = N_NODES;
    while (lo < hi) { int m = (lo + hi) >> 1; if (seg[m] < g) lo = m + 1; else hi = m; }
    int start = lo;
    hi = N_NODES;
    while (lo < hi) { int m = (lo + hi) >> 1; if (seg[m] < g + 1) lo = m + 1; else hi = m; }
    float cnt = (float)(lo - start);
    outg[g * HID + j] /= fmaxf(cnt, 1.0f);
}

__global__ void k_logits(const float* __restrict__ hg, const float* __restrict__ Wc,
                         const float* __restrict__ bc, float* __restrict__ outl) {
    __shared__ float dsh[HID];
    int g = blockIdx.x, t = threadIdx.x;
    dsh[t] = fabsf(hg[g * HID + t] - hg[N_GRAPHS * HID + g * HID + t]);
    __syncthreads();
    if (t < N_CLASSES) {
        float a = bc[t];
        #pragma unroll 8
        for (int k = 0; k < HID; k++) a = fmaf(dsh[k], Wc[k * N_CLASSES + t], a);
        outl[g * N_CLASSES + t] = a;
    }
}

// ---------------- launch ----------------
extern "C" void kernel_launch(void* const* d_in, const int* in_sizes, int n_in,
                              void* d_out, int out_size) {
    const int* src1 = (const int*)d_in[0];
    const int* dst1 = (const int*)d_in[1];
    const int* seg1 = (const int*)d_in[2];
    const int* src2 = (const int*)d_in[3];
    const int* dst2 = (const int*)d_in[4];
    const int* seg2 = (const int*)d_in[5];
    const float* W1 = (const float*)d_in[6];
    const float* b1 = (const float*)d_in[7];
    const float* W2 = (const float*)d_in[8];
    const float* b2 = (const float*)d_in[9];
    const float* W3 = (const float*)d_in[10];
    const float* b3 = (const float*)d_in[11];
    const float* W4 = (const float*)d_in[12];
    const float* b4 = (const float*)d_in[13];
    const float* Wc = (const float*)d_in[14];
    const float* bc = (const float*)d_in[15];
    float* out = (float*)d_out;

    k_zero_out<<<(2 * N_GRAPHS * HID) / 256, 256>>>(out);

    for (int br = 0; br < 2; br++) {
        const int* src = br ? src2 : src1;
        const int* dst = br ? dst2 : dst1;
        const int* seg = br ? seg2 : seg1;

        k_zero_small<<<NBLK, 256>>>();
        k_degree<<<(N_EDGES + 255) / 256, 256>>>(src, dst);

        k_scan1<<<NBLK, 256>>>();
        k_scan2<<<1, 512>>>();
        k_scan3<<<NBLK, 256>>>();
        k_fill<<<(N_EDGES + 255) / 256, 256>>>(src, dst);

        k_agg1<<<NBLK, 256>>>();

        // layer 2 (W2): rank-1 reconstruct gather, writes hsA
        k_layer_first<<<LGRID, 256>>>(W1, b1, W2, b2);
        // layer 3 (W3): hsA -> hsB (applyCs)
        k_layer<<<LGRID, 256>>>(0, W3, b3, 1);
        // layer 4 (W4): hsB -> hsA (no cs)
        k_layer<<<LGRID, 256>>>(1, W4, b4, 0);

        k_pool<<<dim3(N_GRAPHS, NSPLIT), HID>>>(seg, out + br * N_GRAPHS * HID);
        k_pooldiv<<<N_GRAPHS, HID>>>(seg, out + br * N_GRAPHS * HID);
    }
    k_logits<<<N_GRAPHS, HID>>>(out, Wc, bc, out + 2 * N_GRAPHS * HID);
}

// round 6
// speedup vs baseline: 2.5259x; 1.1151x over previous
#include <cuda_runtime.h>
#include <cuda_fp16.h>
#include <math.h>
#include <stdint.h>

#define N_NODES   100000
#define N_EDGES   1600000
#define N_GRAPHS  128
#define HID       128
#define N_CLASSES 10
#define NBLK      391            // ceil(N_NODES/256)
#define BM        64             // nodes per layer block
#define LGRID     ((N_NODES + BM - 1) / BM)
#define NSPLIT    16             // pool node-range splits per graph

// ---------------- scratch (static __device__, no runtime alloc) ----------------
__device__ float  g_deg_out[2][N_NODES];
__device__ float  g_deg_in [2][N_NODES];
__device__ float  g_cs     [2][N_NODES];
__device__ float  g_cd     [2][N_NODES];
__device__ float  g_h1     [2][N_NODES];
__device__ float2 g_x1cs   [2][N_NODES];       // {agg1*cd, cs}
__device__ int    g_rowtmp [2][N_NODES];
__device__ int    g_bsum   [2][512];
__device__ int    g_boff   [2][512];
__device__ int    g_row    [2][N_NODES + 1];
__device__ int    g_cursor [2][N_NODES];
__device__ int    g_csr    [2][N_EDGES];
__device__ __align__(16) unsigned short g_hfA[2][N_NODES * HID];  // fp16 features
__device__ __align__(16) unsigned short g_hfB[2][N_NODES * HID];
__device__ float  g_hsO    [2][N_NODES * HID];  // layer-4 fp32 output (pool input)

// ---------------- packed-math helpers (sm_103a) ----------------
#define FMA2(acc, x, w) \
    asm("fma.rn.f32x2 %0, %1, %2, %3;" : "=l"(acc) : "l"(x), "l"(w), "l"(acc))
#define PACKDUP(d, f) \
    asm("mov.b64 %0, {%1, %1};" : "=l"(d) : "r"(__float_as_uint(f)))
#define UNPACK2(lo, hi, v) \
    asm("mov.b64 {%0, %1}, %2;" : "=r"(lo), "=r"(hi) : "l"(v))

__device__ __forceinline__ uint32_t packhf(float l, float h) {
    __half2 v = __floats2half2_rn(l, h);
    return *(uint32_t*)&v;
}
__device__ __forceinline__ float h_lo(uint32_t w) {
    __half2 v = *(__half2*)&w; return __low2float(v);
}
__device__ __forceinline__ float h_hi(uint32_t w) {
    __half2 v = *(__half2*)&w; return __high2float(v);
}

// ---------------- small kernels ----------------

__global__ void k_zero_out(float* __restrict__ out) {
    int i = blockIdx.x * blockDim.x + threadIdx.x;   // 2*N_GRAPHS*HID = 32768
    out[i] = 0.f;
}

__global__ void k_zero_small() {
    int br = blockIdx.y;
    int i = blockIdx.x * blockDim.x + threadIdx.x;
    if (i < N_NODES) { g_deg_out[br][i] = 0.f; g_deg_in[br][i] = 0.f; }
}

__global__ void k_degree(const int* __restrict__ s1, const int* __restrict__ d1,
                         const int* __restrict__ s2, const int* __restrict__ d2) {
    int br = blockIdx.y;
    const int* src = br ? s2 : s1;
    const int* dst = br ? d2 : d1;
    int e = blockIdx.x * blockDim.x + threadIdx.x;
    if (e < N_EDGES) {
        atomicAdd(&g_deg_out[br][src[e]], 1.0f);
        atomicAdd(&g_deg_in [br][dst[e]], 1.0f);
    }
}

// ---------------- CSR build (prep fused into scan1) ----------------

__global__ void k_scan1() {
    __shared__ int sh[256];
    int br = blockIdx.y;
    int t = threadIdx.x, b = blockIdx.x;
    int i = b * 256 + t;
    int v = 0;
    if (i < N_NODES) {
        float od = g_deg_out[br][i], id = g_deg_in[br][i];
        float cs = rsqrtf(fmaxf(od, 1.0f));
        float cd = rsqrtf(fmaxf(id, 1.0f));
        g_cs[br][i] = cs; g_cd[br][i] = cd;
        g_h1[br][i] = id * cs;
        v = __float2int_rn(id);
    }
    sh[t] = v;
    __syncthreads();
    #pragma unroll
    for (int off = 1; off < 256; off <<= 1) {
        int add = (t >= off) ? sh[t - off] : 0;
        __syncthreads();
        sh[t] += add;
        __syncthreads();
    }
    if (i < N_NODES) g_rowtmp[br][i] = sh[t] - v;
    if (t == 255) g_bsum[br][b] = sh[255];
}

__global__ void k_scan2() {
    __shared__ int sh[512];
    int br = blockIdx.y;
    int t = threadIdx.x;
    int v = (t < NBLK) ? g_bsum[br][t] : 0;
    sh[t] = v;
    __syncthreads();
    #pragma unroll
    for (int off = 1; off < 512; off <<= 1) {
        int add = (t >= off) ? sh[t - off] : 0;
        __syncthreads();
        sh[t] += add;
        __syncthreads();
    }
    g_boff[br][t] = sh[t] - v;
}

__global__ void k_scan3() {
    int br = blockIdx.y;
    int i = blockIdx.x * blockDim.x + threadIdx.x;
    if (i < N_NODES) {
        int r = g_rowtmp[br][i] + g_boff[br][i >> 8];
        g_row[br][i] = r;
        g_cursor[br][i] = r;
    }
    if (i == 0) g_row[br][N_NODES] = N_EDGES;
}

__global__ void k_fill(const int* __restrict__ s1, const int* __restrict__ d1,
                       const int* __restrict__ s2, const int* __restrict__ d2) {
    int br = blockIdx.y;
    const int* src = br ? s2 : s1;
    const int* dst = br ? d2 : d1;
    int e = blockIdx.x * blockDim.x + threadIdx.x;
    if (e < N_EDGES) {
        int pos = atomicAdd(&g_cursor[br][dst[e]], 1);
        g_csr[br][pos] = src[e];
    }
}

// layer-1 scalar aggregation; pack {x1 = agg*cd, cs}
__global__ void k_agg1() {
    int br = blockIdx.y;
    int n = blockIdx.x * blockDim.x + threadIdx.x;
    if (n >= N_NODES) return;
    int s = g_row[br][n], e = g_row[br][n + 1];
    float a = 0.f;
    for (int j = s; j < e; j++) a += g_h1[br][g_csr[br][j]];
    g_x1cs[br][n] = make_float2(a * g_cd[br][n], g_cs[br][n]);
}

// ---------------- GEMM accumulate (packed f32x2) ----------------
__device__ __forceinline__ void gemm_acc(const float* __restrict__ W,
                                         float* xs, float* ws,
                                         int t, uint64_t acc2[4][4]) {
    int cg = (t & 31) * 4;
    int ng = (t >> 5) * 8;

    for (int kc = 0; kc < HID; kc += 16) {
        if (kc) __syncthreads();
        #pragma unroll
        for (int i = 0; i < 2; i++) {
            int idx = t + i * 256;
            ((float4*)ws)[idx] = ((const float4*)(W + kc * HID))[idx];
        }
        __syncthreads();
        #pragma unroll
        for (int kk = 0; kk < 16; kk++) {
            float4 wv = *(const float4*)&ws[kk * HID + cg];
            uint64_t wd0, wd1, wd2, wd3;
            PACKDUP(wd0, wv.x); PACKDUP(wd1, wv.y);
            PACKDUP(wd2, wv.z); PACKDUP(wd3, wv.w);
            const float* xrow = &xs[(kc + kk) * 68 + ng];
            ulonglong2 xa = *(const ulonglong2*)(xrow);
            ulonglong2 xb = *(const ulonglong2*)(xrow + 4);
            FMA2(acc2[0][0], xa.x, wd0); FMA2(acc2[0][1], xa.x, wd1);
            FMA2(acc2[0][2], xa.x, wd2); FMA2(acc2[0][3], xa.x, wd3);
            FMA2(acc2[1][0], xa.y, wd0); FMA2(acc2[1][1], xa.y, wd1);
            FMA2(acc2[1][2], xa.y, wd2); FMA2(acc2[1][3], xa.y, wd3);
            FMA2(acc2[2][0], xb.x, wd0); FMA2(acc2[2][1], xb.x, wd1);
            FMA2(acc2[2][2], xb.x, wd2); FMA2(acc2[2][3], xb.x, wd3);
            FMA2(acc2[3][0], xb.y, wd0); FMA2(acc2[3][1], xb.y, wd1);
            FMA2(acc2[3][2], xb.y, wd2); FMA2(acc2[3][3], xb.y, wd3);
        }
    }
}

// ---------------- layer 2 (W2): rank-1 reconstruct gather + GEMM -> fp16 hfA ----------------
__global__ void __launch_bounds__(256) k_layer_first(const float* __restrict__ W1,
                                                     const float* __restrict__ B1,
                                                     const float* __restrict__ W,
                                                     const float* __restrict__ bb) {
    __shared__ float xs[HID * 68];
    __shared__ float ws[16 * HID];
    __shared__ float cdm[BM], csm[BM];

    int br = blockIdx.y;
    int t = threadIdx.x;
    int nbase = blockIdx.x * BM;
    if (t < BM) {
        int n = nbase + t;
        cdm[t] = (n < N_NODES) ? g_cd[br][n] : 0.f;
        csm[t] = (n < N_NODES) ? g_cs[br][n] : 0.f;
    }
    __syncthreads();

    {
        int warp = t >> 5, lane = t & 31;
        int kb = lane * 4;
        float4 w1  = *(const float4*)(W1 + kb);
        float4 b1v = *(const float4*)(B1 + kb);
        const float2* x1 = g_x1cs[br];
        const int* csr = g_csr[br];
        #pragma unroll
        for (int q = 0; q < 8; q++) {
            int nl = warp * 8 + q;
            int n  = nbase + nl;
            float4 acc = make_float4(0.f, 0.f, 0.f, 0.f);
            if (n < N_NODES) {
                int s = g_row[br][n], e = g_row[br][n + 1];
                int j = s;
                for (; j + 4 <= e; j += 4) {
                    float2 p0 = x1[csr[j]];
                    float2 p1 = x1[csr[j+1]];
                    float2 p2 = x1[csr[j+2]];
                    float2 p3 = x1[csr[j+3]];
                    acc.x += fmaxf(fmaf(p0.x, w1.x, b1v.x), 0.f) * p0.y
                           + fmaxf(fmaf(p1.x, w1.x, b1v.x), 0.f) * p1.y
                           + fmaxf(fmaf(p2.x, w1.x, b1v.x), 0.f) * p2.y
                           + fmaxf(fmaf(p3.x, w1.x, b1v.x), 0.f) * p3.y;
                    acc.y += fmaxf(fmaf(p0.x, w1.y, b1v.y), 0.f) * p0.y
                           + fmaxf(fmaf(p1.x, w1.y, b1v.y), 0.f) * p1.y
                           + fmaxf(fmaf(p2.x, w1.y, b1v.y), 0.f) * p2.y
                           + fmaxf(fmaf(p3.x, w1.y, b1v.y), 0.f) * p3.y;
                    acc.z += fmaxf(fmaf(p0.x, w1.z, b1v.z), 0.f) * p0.y
                           + fmaxf(fmaf(p1.x, w1.z, b1v.z), 0.f) * p1.y
                           + fmaxf(fmaf(p2.x, w1.z, b1v.z), 0.f) * p2.y
                           + fmaxf(fmaf(p3.x, w1.z, b1v.z), 0.f) * p3.y;
                    acc.w += fmaxf(fmaf(p0.x, w1.w, b1v.w), 0.f) * p0.y
                           + fmaxf(fmaf(p1.x, w1.w, b1v.w), 0.f) * p1.y
                           + fmaxf(fmaf(p2.x, w1.w, b1v.w), 0.f) * p2.y
                           + fmaxf(fmaf(p3.x, w1.w, b1v.w), 0.f) * p3.y;
                }
                for (; j < e; j++) {
                    float2 p = x1[csr[j]];
                    acc.x += fmaxf(fmaf(p.x, w1.x, b1v.x), 0.f) * p.y;
                    acc.y += fmaxf(fmaf(p.x, w1.y, b1v.y), 0.f) * p.y;
                    acc.z += fmaxf(fmaf(p.x, w1.z, b1v.z), 0.f) * p.y;
                    acc.w += fmaxf(fmaf(p.x, w1.w, b1v.w), 0.f) * p.y;
                }
            }
            float cdv = cdm[nl];
            xs[(kb + 0) * 68 + nl] = acc.x * cdv;
            xs[(kb + 1) * 68 + nl] = acc.y * cdv;
            xs[(kb + 2) * 68 + nl] = acc.z * cdv;
            xs[(kb + 3) * 68 + nl] = acc.w * cdv;
        }
    }
    __syncthreads();

    uint64_t acc2[4][4];
    #pragma unroll
    for (int p = 0; p < 4; p++)
        #pragma unroll
        for (int c = 0; c < 4; c++) acc2[p][c] = 0ull;
    gemm_acc(W, xs, ws, t, acc2);

    int cg = (t & 31) * 4;
    int ng = (t >> 5) * 8;
    float4 bv = *(const float4*)&bb[cg];
    uint2* outb = (uint2*)g_hfA[br];
    #pragma unroll
    for (int p = 0; p < 4; p++) {
        int nl0 = ng + 2 * p;
        uint32_t lo0, hi0, lo1, hi1, lo2, hi2, lo3, hi3;
        UNPACK2(lo0, hi0, acc2[p][0]);
        UNPACK2(lo1, hi1, acc2[p][1]);
        UNPACK2(lo2, hi2, acc2[p][2]);
        UNPACK2(lo3, hi3, acc2[p][3]);
        int n0 = nbase + nl0, n1 = n0 + 1;
        if (n0 < N_NODES) {
            float sc = csm[nl0];
            float ox = fmaxf(__uint_as_float(lo0) + bv.x, 0.f) * sc;
            float oy = fmaxf(__uint_as_float(lo1) + bv.y, 0.f) * sc;
            float oz = fmaxf(__uint_as_float(lo2) + bv.z, 0.f) * sc;
            float ow = fmaxf(__uint_as_float(lo3) + bv.w, 0.f) * sc;
            uint2 v; v.x = packhf(ox, oy); v.y = packhf(oz, ow);
            outb[(n0 * HID + cg) >> 2] = v;
        }
        if (n1 < N_NODES) {
            float sc = csm[nl0 + 1];
            float ox = fmaxf(__uint_as_float(hi0) + bv.x, 0.f) * sc;
            float oy = fmaxf(__uint_as_float(hi1) + bv.y, 0.f) * sc;
            float oz = fmaxf(__uint_as_float(hi2) + bv.z, 0.f) * sc;
            float ow = fmaxf(__uint_as_float(hi3) + bv.w, 0.f) * sc;
            uint2 v; v.x = packhf(ox, oy); v.y = packhf(oz, ow);
            outb[(n1 * HID + cg) >> 2] = v;
        }
    }
}

// ---------------- layers 3/4: fp16 row gather + GEMM ----------------
// lvl=0: in hfA -> out hfB (fp16, *cs) ; lvl=1: in hfB -> out hsO (fp32, no cs)
__global__ void __launch_bounds__(256) k_layer(int lvl,
                                               const float* __restrict__ W,
                                               const float* __restrict__ bb) {
    __shared__ float xs[HID * 68];
    __shared__ float ws[16 * HID];
    __shared__ float cdm[BM], csm[BM];

    int br = blockIdx.y;
    const uint2* in2 = (const uint2*)(lvl ? g_hfB[br] : g_hfA[br]);

    int t = threadIdx.x;
    int nbase = blockIdx.x * BM;
    if (t < BM) {
        int n = nbase + t;
        cdm[t] = (n < N_NODES) ? g_cd[br][n] : 0.f;
        csm[t] = (n < N_NODES) ? g_cs[br][n] : 0.f;
    }
    __syncthreads();

    {
        int warp = t >> 5, lane = t & 31;
        const int* csr = g_csr[br];
        #pragma unroll
        for (int q = 0; q < 8; q++) {
            int nl = warp * 8 + q;
            int n  = nbase + nl;
            float4 acc = make_float4(0.f, 0.f, 0.f, 0.f);
            if (n < N_NODES) {
                int s = g_row[br][n], e = g_row[br][n + 1];
                int j = s;
                for (; j + 4 <= e; j += 4) {
                    int s0 = csr[j], s1 = csr[j+1], s2 = csr[j+2], s3 = csr[j+3];
                    uint2 v0 = in2[s0 * 32 + lane];
                    uint2 v1 = in2[s1 * 32 + lane];
                    uint2 v2 = in2[s2 * 32 + lane];
                    uint2 v3 = in2[s3 * 32 + lane];
                    acc.x += (h_lo(v0.x) + h_lo(v1.x)) + (h_lo(v2.x) + h_lo(v3.x));
                    acc.y += (h_hi(v0.x) + h_hi(v1.x)) + (h_hi(v2.x) + h_hi(v3.x));
                    acc.z += (h_lo(v0.y) + h_lo(v1.y)) + (h_lo(v2.y) + h_lo(v3.y));
                    acc.w += (h_hi(v0.y) + h_hi(v1.y)) + (h_hi(v2.y) + h_hi(v3.y));
                }
                for (; j < e; j++) {
                    uint2 v = in2[csr[j] * 32 + lane];
                    acc.x += h_lo(v.x); acc.y += h_hi(v.x);
                    acc.z += h_lo(v.y); acc.w += h_hi(v.y);
                }
            }
            float cdv = cdm[nl];
            int kb = lane * 4;
            xs[(kb + 0) * 68 + nl] = acc.x * cdv;
            xs[(kb + 1) * 68 + nl] = acc.y * cdv;
            xs[(kb + 2) * 68 + nl] = acc.z * cdv;
            xs[(kb + 3) * 68 + nl] = acc.w * cdv;
        }
    }
    __syncthreads();

    uint64_t acc2[4][4];
    #pragma unroll
    for (int p = 0; p < 4; p++)
        #pragma unroll
        for (int c = 0; c < 4; c++) acc2[p][c] = 0ull;
    gemm_acc(W, xs, ws, t, acc2);

    int cg = (t & 31) * 4;
    int ng = (t >> 5) * 8;
    float4 bv = *(const float4*)&bb[cg];
    uint2*  outb = (uint2*)g_hfB[br];
    float*  outf = g_hsO[br];
    #pragma unroll
    for (int p = 0; p < 4; p++) {
        int nl0 = ng + 2 * p;
        uint32_t lo0, hi0, lo1, hi1, lo2, hi2, lo3, hi3;
        UNPACK2(lo0, hi0, acc2[p][0]);
        UNPACK2(lo1, hi1, acc2[p][1]);
        UNPACK2(lo2, hi2, acc2[p][2]);
        UNPACK2(lo3, hi3, acc2[p][3]);
        int n0 = nbase + nl0, n1 = n0 + 1;
        #pragma unroll
        for (int h = 0; h < 2; h++) {
            int n = h ? n1 : n0;
            if (n >= N_NODES) continue;
            float a0 = __uint_as_float(h ? hi0 : lo0) + bv.x;
            float a1 = __uint_as_float(h ? hi1 : lo1) + bv.y;
            float a2 = __uint_as_float(h ? hi2 : lo2) + bv.z;
            float a3 = __uint_as_float(h ? hi3 : lo3) + bv.w;
            if (lvl == 0) {
                float sc = csm[nl0 + h];
                float ox = fmaxf(a0, 0.f) * sc;
                float oy = fmaxf(a1, 0.f) * sc;
                float oz = fmaxf(a2, 0.f) * sc;
                float ow = fmaxf(a3, 0.f) * sc;
                uint2 v; v.x = packhf(ox, oy); v.y = packhf(oz, ow);
                outb[(n * HID + cg) >> 2] = v;
            } else {
                float4 o;
                o.x = fmaxf(a0, 0.f); o.y = fmaxf(a1, 0.f);
                o.z = fmaxf(a2, 0.f); o.w = fmaxf(a3, 0.f);
                *(float4*)&outf[n * HID + cg] = o;
            }
        }
    }
}

// ---------------- pooling (parallel, atomic partials into pre-zeroed out) ----------------

__global__ void k_pool(const int* __restrict__ sg1, const int* __restrict__ sg2,
                       float* __restrict__ out) {
    int br = blockIdx.z;
    const int* seg = br ? sg2 : sg1;
    float* outg = out + br * N_GRAPHS * HID;
    const float* hs = g_hsO[br];
    int g = blockIdx.x, slice = blockIdx.y, j = threadIdx.x;
    int lo = 0, hi = N_NODES;
    while (lo < hi) { int m = (lo + hi) >> 1; if (seg[m] < g) lo = m + 1; else hi = m; }
    int start = lo;
    hi = N_NODES;
    while (lo < hi) { int m = (lo + hi) >> 1; if (seg[m] < g + 1) lo = m + 1; else hi = m; }
    int end = lo;
    int len = end - start;
    int s0 = start + (int)(((long long)len * slice) / NSPLIT);
    int s1 = start + (int)(((long long)len * (slice + 1)) / NSPLIT);
    float s = 0.f;
    for (int n = s0; n < s1; n++) s += hs[n * HID + j];
    if (s1 > s0) atomicAdd(&outg[g * HID + j], s);
}

__global__ void k_pooldiv(const int* __restrict__ sg1, const int* __restrict__ sg2,
                          float* __restrict__ out) {
    int br = blockIdx.y;
    const int* seg = br ? sg2 : sg1;
    float* outg = out + br * N_GRAPHS * HID;
    int g = blockIdx.x, j = threadIdx.x;
    int lo = 0, hi = N_NODES;
    while (lo < hi) { int m = (lo + hi) >> 1; if (seg[m] < g) lo = m + 1; else hi = m; }
    int start = lo;
    hi = N_NODES;
    while (lo < hi) { int m = (lo + hi) >> 1; if (seg[m] < g + 1) lo = m + 1; else hi = m; }
    float cnt = (float)(lo - start);
    outg[g * HID + j] /= fmaxf(cnt, 1.0f);
}

__global__ void k_logits(const float* __restrict__ hg, const float* __restrict__ Wc,
                         const float* __restrict__ bc, float* __restrict__ outl) {
    __shared__ float dsh[HID];
    int g = blockIdx.x, t = threadIdx.x;
    dsh[t] = fabsf(hg[g * HID + t] - hg[N_GRAPHS * HID + g * HID + t]);
    __syncthreads();
    if (t < N_CLASSES) {
        float a = bc[t];
        #pragma unroll 8
        for (int k = 0; k < HID; k++) a = fmaf(dsh[k], Wc[k * N_CLASSES + t], a);
        outl[g * N_CLASSES + t] = a;
    }
}

// ---------------- launch ----------------
extern "C" void kernel_launch(void* const* d_in, const int* in_sizes, int n_in,
                              void* d_out, int out_size) {
    const int* src1 = (const int*)d_in[0];
    const int* dst1 = (const int*)d_in[1];
    const int* seg1 = (const int*)d_in[2];
    const int* src2 = (const int*)d_in[3];
    const int* dst2 = (const int*)d_in[4];
    const int* seg2 = (const int*)d_in[5];
    const float* W1 = (const float*)d_in[6];
    const float* b1 = (const float*)d_in[7];
    const float* W2 = (const float*)d_in[8];
    const float* b2 = (const float*)d_in[9];
    const float* W3 = (const float*)d_in[10];
    const float* b3 = (const float*)d_in[11];
    const float* W4 = (const float*)d_in[12];
    const float* b4 = (const float*)d_in[13];
    const float* Wc = (const float*)d_in[14];
    const float* bc = (const float*)d_in[15];
    float* out = (float*)d_out;

    k_zero_out<<<(2 * N_GRAPHS * HID) / 256, 256>>>(out);
    k_zero_small<<<dim3(NBLK, 2), 256>>>();
    k_degree<<<dim3((N_EDGES + 255) / 256, 2), 256>>>(src1, dst1, src2, dst2);

    k_scan1<<<dim3(NBLK, 2), 256>>>();
    k_scan2<<<dim3(1, 2), 512>>>();
    k_scan3<<<dim3(NBLK, 2), 256>>>();
    k_fill<<<dim3((N_EDGES + 255) / 256, 2), 256>>>(src1, dst1, src2, dst2);

    k_agg1<<<dim3(NBLK, 2), 256>>>();

    k_layer_first<<<dim3(LGRID, 2), 256>>>(W1, b1, W2, b2);
    k_layer<<<dim3(LGRID, 2), 256>>>(0, W3, b3);
    k_layer<<<dim3(LGRID, 2), 256>>>(1, W4, b4);

    k_pool<<<dim3(N_GRAPHS, NSPLIT, 2), HID>>>(seg1, seg2, out);
    k_pooldiv<<<dim3(N_GRAPHS, 2), HID>>>(seg1, seg2, out);
    k_logits<<<N_GRAPHS, HID>>>(out, Wc, bc, out + 2 * N_GRAPHS * HID);
}